// round 5
// baseline (speedup 1.0000x reference)
#include <cuda_runtime.h>
#include <cstdint>

// QuantumKANRegressor: out[b] = sum_f sum_j kan[f,j] * T_j( tanh( sum_k w[f,k]*T_{k+1}(X[b,f]) / sum_k|w[f,k]| ) )
// B=65536, F=64, DEG=16 (T_1..T_16), KAN_DEG=5 (T_0..T_5)
//
// R5: feature-packed f32x2 weights in REGISTERS (44 regs), R=2 rows in flight
// so total register demand stays under the 128-reg cap (R4's R=4 spilled the
// weight array to local memory -> L1-bound). Prefetch + folded reduction kept.

typedef unsigned long long ull;

__device__ __forceinline__ ull pk2(float lo, float hi) {
    ull d; asm("mov.b64 %0, {%1, %2};" : "=l"(d) : "f"(lo), "f"(hi)); return d;
}
__device__ __forceinline__ void upk2(ull v, float& lo, float& hi) {
    asm("mov.b64 {%0, %1}, %2;" : "=f"(lo), "=f"(hi) : "l"(v));
}
__device__ __forceinline__ ull fma2(ull a, ull b, ull c) {
    ull d; asm("fma.rn.f32x2 %0, %1, %2, %3;" : "=l"(d) : "l"(a), "l"(b), "l"(c)); return d;
}
__device__ __forceinline__ ull add2(ull a, ull b) {
    ull d; asm("add.rn.f32x2 %0, %1, %2;" : "=l"(d) : "l"(a), "l"(b)); return d;
}
__device__ __forceinline__ ull mul2(ull a, ull b) {
    ull d; asm("mul.rn.f32x2 %0, %1, %2;" : "=l"(d) : "l"(a), "l"(b)); return d;
}
__device__ __forceinline__ float ex2f(float x) {
    float y; asm("ex2.approx.f32 %0, %1;" : "=f"(y) : "f"(x)); return y;
}
__device__ __forceinline__ float rcpf(float x) {
    float y; asm("rcp.approx.f32 %0, %1;" : "=f"(y) : "f"(x)); return y;
}
// tanh(f) = 1 - 2/(1 + exp(2f)); exp via ex2 (MUFU). ~1e-6 abs error on |f|<=1.
__device__ __forceinline__ float tanh_fast(float f) {
    float e = ex2f(f * 2.8853900817779268f);   // 2 * log2(e)
    float r = rcpf(e + 1.0f);
    return fmaf(-2.0f, r, 1.0f);
}

static constexpr int F    = 64;
static constexpr int DEG  = 16;
static constexpr int NBLK = 296;   // 2 CTAs/SM * 148 SMs
static constexpr int NTHR = 256;

__global__ void __launch_bounds__(NTHR, 2)
qkan_kernel(const float* __restrict__ X,
            const float* __restrict__ W,    // [F, DEG]
            const float* __restrict__ KC,   // [1, F, 6]
            float* __restrict__ out,        // [B]
            int B)
{
    const int tid  = threadIdx.x;
    const int lane = tid & 31;

    // -------- per-thread weight preprocessing (once) --------
    // Lane owns features f0 = 2*lane, f1 = 2*lane+1, packed as (f0, f1).
    // Sign-folded Chebyshev: X_k = s_k*T_k, s_k = -1 for k mod 4 in {2,3};
    // recurrence X_j = fma( (j odd ? +2x : -2x), X_{j-1}, X_{j-2} ).
    // Folded weight: w'_k = lcu[f][k-1] * s_k / denom[f].
    ull wq[DEG];   // packed (w'_{f0,k}, w'_{f1,k}) -- stays in registers (44 total)
    ull pc[6];     // packed KAN monomial (Horner) coefficients per feature
    {
        float wv[2][DEG];
        float rd[2];
        #pragma unroll
        for (int i = 0; i < 2; ++i) {
            const int f = 2 * lane + i;
            float den = 0.0f;
            #pragma unroll
            for (int k = 0; k < DEG; ++k) { wv[i][k] = __ldg(W + f * DEG + k); den += fabsf(wv[i][k]); }
            rd[i] = 1.0f / den;
        }
        #pragma unroll
        for (int k = 0; k < DEG; ++k) {
            const int kk = k + 1;
            float v0 = wv[0][k] * rd[0];
            float v1 = wv[1][k] * rd[1];
            if (kk & 2) { v0 = -v0; v1 = -v1; }
            wq[k] = pk2(v0, v1);
        }
        // KAN Chebyshev (deg 5) -> monomial Horner coefficients, per feature
        float pm[2][6];
        #pragma unroll
        for (int i = 0; i < 2; ++i) {
            const int f = 2 * lane + i;
            const float k0 = __ldg(KC + f*6+0), k1 = __ldg(KC + f*6+1), k2 = __ldg(KC + f*6+2);
            const float k3 = __ldg(KC + f*6+3), k4 = __ldg(KC + f*6+4), k5 = __ldg(KC + f*6+5);
            pm[i][0] = k0 - k2 + k4;
            pm[i][1] = k1 - 3.0f*k3 + 5.0f*k5;
            pm[i][2] = 2.0f*k2 - 8.0f*k4;
            pm[i][3] = 4.0f*k3 - 20.0f*k5;
            pm[i][4] = 8.0f*k4;
            pm[i][5] = 16.0f*k5;
        }
        #pragma unroll
        for (int k = 0; k < 6; ++k) pc[k] = pk2(pm[0][k], pm[1][k]);
    }

    const ull ONE2  = 0x3F8000003F800000ull;   // (1.0f, 1.0f)
    const ull NEG22 = 0xC0000000C0000000ull;   // (-2.0f, -2.0f)

    const int gw = (blockIdx.x * NTHR + tid) >> 5;
    const int nW = (gridDim.x * NTHR) >> 5;
    const int nG = B / 2;                      // 2 rows per group

    // ---- prefetch first group (2 rows, lane reads its feature pair) ----
    int g = gw;
    float2 cx0, cx1;
    if (g < nG) {
        const float2* base = (const float2*)X + (size_t)(2 * g) * 32 + lane;
        cx0 = __ldg(base);
        cx1 = __ldg(base + 32);
    }

    while (g < nG) {
        const int gn = g + nW;
        float2 nx0, nx1;
        if (gn < nG) {
            const float2* base = (const float2*)X + (size_t)(2 * gn) * 32 + lane;
            nx0 = __ldg(base);
            nx1 = __ldg(base + 32);
        }

        // ---- two independent row chains (explicit scalars, no arrays) ----
        const ull x0   = pk2(cx0.x, cx0.y);
        const ull x1   = pk2(cx1.x, cx1.y);
        const ull p2x0 = add2(x0, x0),     p2x1 = add2(x1, x1);
        const ull m2x0 = mul2(x0, NEG22),  m2x1 = mul2(x1, NEG22);
        ull Xa0 = x0,                      Xa1 = x1;
        ull Xb0 = fma2(m2x0, x0, ONE2);
        ull Xb1 = fma2(m2x1, x1, ONE2);
        ull f0  = mul2(wq[0], Xa0);
        ull f1  = mul2(wq[0], Xa1);
        f0 = fma2(wq[1], Xb0, f0);
        f1 = fma2(wq[1], Xb1, f1);
        #pragma unroll
        for (int j = 3; j <= DEG; ++j) {
            const ull Xc0 = fma2((j & 1) ? p2x0 : m2x0, Xb0, Xa0);
            const ull Xc1 = fma2((j & 1) ? p2x1 : m2x1, Xb1, Xa1);
            f0 = fma2(wq[j - 1], Xc0, f0);
            f1 = fma2(wq[j - 1], Xc1, f1);
            Xa0 = Xb0; Xb0 = Xc0;
            Xa1 = Xb1; Xb1 = Xc1;
        }
        // tanh (MUFU) then deg-5 Horner per packed feature pair
        float l0, h0, l1, h1;
        upk2(f0, l0, h0); upk2(f1, l1, h1);
        const ull z0 = pk2(tanh_fast(l0), tanh_fast(h0));
        const ull z1 = pk2(tanh_fast(l1), tanh_fast(h1));
        ull t0 = fma2(pc[5], z0, pc[4]);
        ull t1 = fma2(pc[5], z1, pc[4]);
        t0 = fma2(t0, z0, pc[3]); t1 = fma2(t1, z1, pc[3]);
        t0 = fma2(t0, z0, pc[2]); t1 = fma2(t1, z1, pc[2]);
        t0 = fma2(t0, z0, pc[1]); t1 = fma2(t1, z1, pc[1]);
        t0 = fma2(t0, z0, pc[0]); t1 = fma2(t1, z1, pc[0]);
        float s0lo, s0hi, s1lo, s1hi;
        upk2(t0, s0lo, s0hi); upk2(t1, s1lo, s1hi);
        const float s0 = s0lo + s0hi;          // row 2g   partial (lane's 2 feats)
        const float s1 = s1lo + s1hi;          // row 2g+1 partial

        // ---- warp reduction: pack (row0, row1), 5-level 64-bit tree ----
        {
            ull m = pk2(s0, s1);
            #pragma unroll
            for (int off = 16; off; off >>= 1)
                m = add2(m, __shfl_xor_sync(0xffffffffu, m, off));
            if (lane == 0) {
                float lo, hi; upk2(m, lo, hi);
                ((float2*)out)[g] = make_float2(lo, hi);
            }
        }

        cx0 = nx0; cx1 = nx1;
        g = gn;
    }
}

extern "C" void kernel_launch(void* const* d_in, const int* in_sizes, int n_in,
                              void* d_out, int out_size)
{
    const float* X  = (const float*)d_in[0];   // [B, 64] fp32
    const float* W  = (const float*)d_in[1];   // [64, 16] fp32
    const float* KC = (const float*)d_in[2];   // [1, 64, 6] fp32
    float* out = (float*)d_out;                // [B] fp32

    const int B = in_sizes[0] / F;             // 65536

    qkan_kernel<<<NBLK, NTHR>>>(X, W, KC, out, B);
}